// round 8
// baseline (speedup 1.0000x reference)
#include <cuda_runtime.h>
#include <cuda_bf16.h>
#include <cstdint>

// RWKV WKV recurrence, single-pass serial-in-T, warp-per-block cp.async ring.
//   a_t = exp(w_t)*a_{t-1} + exp(k_t)
//   b_t = exp(w_t)*b_{t-1} + exp(k_t)*v_t
//   out_t = b_t / a_t
// R7: R5's proven pipeline shape (SPB=8, NB=8, recomputed cp.async addressing,
// 48-step prefetch lead) but TWO chains per thread via float2: one 32-thread
// block owns a 64-wide d-group (256 blocks total). LDS.64/STG.64 halve the
// per-element instruction cost; per-warp in-flight demand doubles (~36KB).
// Minimal traffic: 3 reads + 1 write = 537MB.

#define BATCH 16
#define TLEN  2048
#define DIM   1024
#define GD    64                       // d-elements per block
#define NT    32                       // threads per block
#define SPB   8                        // steps per ring slot
#define NB    8                        // ring depth (48-step lead at wait 6)
#define NBT   (TLEN / SPB)             // 256 iterations
#define TPT   12                       // cp.async 16B tiles per thread per slot
                                       //  = 3 arr * 8 steps * (256B/16B) / 32
#define ROWF  GD                       // floats per ring row

__device__ __forceinline__ void cp_async16(uint32_t s, const void* g) {
    asm volatile("cp.async.cg.shared.global [%0], [%1], 16;" :: "r"(s), "l"(g));
}

__global__ __launch_bounds__(NT, 4)
void wkv_warp2_ring_kernel(const float* __restrict__ K,
                           const float* __restrict__ V,
                           const float* __restrict__ W,
                           float* __restrict__ O) {
    // ring[slot][arr][step][d] : slot<8, arr<3, step<8, d<64  -> 48 KB
    __shared__ float ring[NB * 3 * SPB * ROWF];

    const int tid = threadIdx.x;
    const int b   = blockIdx.x >> 4;          // batch
    const int g   = blockIdx.x & 15;          // 64-wide d-group

    const size_t rowBase = (size_t)b * TLEN * DIM + (size_t)g * GD;
    const uint32_t sBase = (uint32_t)__cvta_generic_to_shared(ring);

    const float* arrs[3] = { K, V, W };

    // Issue all cp.asyncs for one ring slot (R5-style recomputed addressing:
    // cheap ALU in the issue loop, low register footprint).
    auto issue_batch = [&](int bt) {
        const int slot = bt & (NB - 1);
        const int step0 = bt * SPB;
#pragma unroll
        for (int j = 0; j < TPT; j++) {
            int i   = tid + NT * j;           // 0..383
            int arr = i >> 7;                 // /128 (8 steps * 16 cols per array)
            int rem = i & 127;
            int t   = rem >> 4;               // step within slot
            int col = rem & 15;               // 16B column within 256B row
            size_t goff = rowBase + (size_t)(step0 + t) * DIM + (size_t)col * 4;
            uint32_t soff = (uint32_t)((((slot * 3 + arr) * SPB + t) * ROWF + col * 4) * 4);
            cp_async16(sBase + soff, arrs[arr] + goff);
        }
    };

    // ---- prologue: fill NB-1 ring slots ----
#pragma unroll
    for (int bt = 0; bt < NB - 1; bt++) {
        issue_batch(bt);
        asm volatile("cp.async.commit_group;");
    }

    float a0 = 0.0f, s0 = 0.0f;   // chain d = 2*tid
    float a1 = 0.0f, s1 = 0.0f;   // chain d = 2*tid+1
    float2* out = (float2*)(O + rowBase + 2 * tid);

    for (int bt = 0; bt < NBT; bt++) {
        // Keep pipeline full; commit every iteration (possibly empty group)
        // so wait_group arithmetic stays uniform through the tail.
        if (bt + NB - 1 < NBT) issue_batch(bt + NB - 1);
        asm volatile("cp.async.commit_group;");
        asm volatile("cp.async.wait_group %0;" :: "n"(NB - 2) : "memory");
        __syncwarp();   // this slot's data visible to all lanes

        const int slot = bt & (NB - 1);
        const float2* rk = (const float2*)&ring[((slot * 3 + 0) * SPB) * ROWF + 2 * tid];
        const float2* rv = (const float2*)&ring[((slot * 3 + 1) * SPB) * ROWF + 2 * tid];
        const float2* rw = (const float2*)&ring[((slot * 3 + 2) * SPB) * ROWF + 2 * tid];

#pragma unroll
        for (int u = 0; u < SPB; u++) {
            float2 lk = rk[u * (ROWF / 2)];
            float2 lv = rv[u * (ROWF / 2)];
            float2 lw = rw[u * (ROWF / 2)];
            float ek0 = __expf(lk.x), ek1 = __expf(lk.y);
            float ew0 = __expf(lw.x), ew1 = __expf(lw.y);
            a0 = fmaf(ew0, a0, ek0);
            s0 = fmaf(ew0, s0, ek0 * lv.x);
            a1 = fmaf(ew1, a1, ek1);
            s1 = fmaf(ew1, s1, ek1 * lv.y);
            float2 r = make_float2(__fdividef(s0, a0), __fdividef(s1, a1));
            __stcs(&out[(size_t)(bt * SPB + u) * (DIM / 2)], r);
        }
        __syncwarp();   // all lanes done reading before slot is overwritten
    }
}

extern "C" void kernel_launch(void* const* d_in, const int* in_sizes, int n_in,
                              void* d_out, int out_size) {
    const float* k = (const float*)d_in[0];
    const float* v = (const float*)d_in[1];
    const float* w = (const float*)d_in[2];
    float* out = (float*)d_out;

    wkv_warp2_ring_kernel<<<BATCH * (DIM / GD), NT>>>(k, v, w, out);
}

// round 11
// speedup vs baseline: 1.0599x; 1.0599x over previous
#include <cuda_runtime.h>
#include <cuda_bf16.h>
#include <cstdint>

// RWKV WKV recurrence, single-pass serial-in-T, warp-per-block cp.async ring.
//   a_t = exp(w_t)*a_{t-1} + exp(k_t)
//   b_t = exp(w_t)*b_{t-1} + exp(k_t)*v_t
//   out_t = b_t / a_t
// One 32-thread block per (batch, 32-wide d-group): 512 blocks / 512 warps
// (proven optimal in R5-R7). R8 change: ring depth NB 8->16 (48KB smem, the
// static limit) -> prefetch lead 45KB/warp (~23MB chip-wide), to out-run the
// queueing-inflated DRAM latency at ~80% utilization. Steady-state work per
// iteration is identical to the 82.4us R6 kernel.
// Minimal traffic: 3 reads + 1 write = 537MB.

#define BATCH 16
#define TLEN  2048
#define DIM   1024
#define GROUP 32
#define SPB   8                        // steps per ring slot
#define NB    16                       // ring depth in slots (120-step lead)
#define NBT   (TLEN / SPB)             // 256 iterations
#define TILES_PER_BATCH (3 * SPB * (GROUP * 4 / 16))   // 3 * 8 * 8 = 192
#define TILES_PER_THREAD (TILES_PER_BATCH / GROUP)     // 6

__device__ __forceinline__ void cp_async16(uint32_t s, const void* g) {
    asm volatile("cp.async.cg.shared.global [%0], [%1], 16;" :: "r"(s), "l"(g));
}

__global__ __launch_bounds__(GROUP, 4)
void wkv_warp_ring_kernel(const float* __restrict__ K,
                          const float* __restrict__ V,
                          const float* __restrict__ W,
                          float* __restrict__ O) {
    // ring[slot][arr][step][d] : slot<16, arr<3, step<8, d<32  -> 49152 B
    __shared__ float ring[NB * 3 * SPB * GROUP];

    const int tid = threadIdx.x;
    const int b   = blockIdx.x >> 5;          // batch
    const int g   = blockIdx.x & 31;          // d-group of 32

    const size_t rowBase = (size_t)b * TLEN * DIM + (size_t)g * GROUP;
    const uint32_t sBase = (uint32_t)__cvta_generic_to_shared(ring);

    const float* arrs[3] = { K, V, W };

    // Issue all cp.asyncs for one ring slot (8 steps x 3 arrays x 128B rows).
    auto issue_batch = [&](int bt) {
        const int slot = bt & (NB - 1);
        const int step0 = bt * SPB;
#pragma unroll
        for (int j = 0; j < TILES_PER_THREAD; j++) {
            int i   = tid + GROUP * j;        // 0..191
            int arr = i >> 6;                 // /64  (8 tiles * 8 steps per array)
            int rem = i & 63;
            int t   = rem >> 3;               // step within slot
            int col = rem & 7;                // 16B column within 128B row
            size_t goff = rowBase + (size_t)(step0 + t) * DIM + (size_t)col * 4;
            uint32_t soff = (uint32_t)((((slot * 3 + arr) * SPB + t) * GROUP + col * 4) * 4);
            cp_async16(sBase + soff, arrs[arr] + goff);
        }
    };

    // ---- prologue: fill NB-1 ring slots ----
#pragma unroll
    for (int bt = 0; bt < NB - 1; bt++) {
        issue_batch(bt);
        asm volatile("cp.async.commit_group;");
    }

    float a = 0.0f, s = 0.0f;
    float* out = O + rowBase + tid;

    for (int bt = 0; bt < NBT; bt++) {
        // Keep pipeline full; commit every iteration (possibly empty group)
        // so wait_group arithmetic stays uniform through the tail.
        if (bt + NB - 1 < NBT) issue_batch(bt + NB - 1);
        asm volatile("cp.async.commit_group;");
        asm volatile("cp.async.wait_group %0;" :: "n"(NB - 2) : "memory");
        __syncwarp();   // this slot's data visible to all lanes

        const int slot = bt & (NB - 1);
        const float* rk = &ring[((slot * 3 + 0) * SPB) * GROUP + tid];
        const float* rv = &ring[((slot * 3 + 1) * SPB) * GROUP + tid];
        const float* rw = &ring[((slot * 3 + 2) * SPB) * GROUP + tid];

#pragma unroll
        for (int u = 0; u < SPB; u++) {
            float lk = rk[u * GROUP];
            float lv = rv[u * GROUP];
            float lw = rw[u * GROUP];
            float ek = __expf(lk);
            float ew = __expf(lw);
            a = fmaf(ew, a, ek);
            s = fmaf(ew, s, ek * lv);
            __stcs(&out[(size_t)(bt * SPB + u) * DIM], __fdividef(s, a));
        }
        __syncwarp();   // all lanes done reading before slot is overwritten
    }
}

extern "C" void kernel_launch(void* const* d_in, const int* in_sizes, int n_in,
                              void* d_out, int out_size) {
    const float* k = (const float*)d_in[0];
    const float* v = (const float*)d_in[1];
    const float* w = (const float*)d_in[2];
    float* out = (float*)d_out;

    wkv_warp_ring_kernel<<<BATCH * (DIM / GROUP), GROUP>>>(k, v, w, out);
}

// round 12
// speedup vs baseline: 1.1681x; 1.1021x over previous
#include <cuda_runtime.h>
#include <cuda_bf16.h>
#include <cstdint>

// RWKV WKV recurrence, single-pass serial-in-T, warp-per-block cp.async ring.
//   a_t = exp(w_t)*a_{t-1} + exp(k_t)
//   b_t = exp(w_t)*b_{t-1} + exp(k_t)*v_t
//   out_t = b_t / a_t
// One 32-thread block per (batch, 32-wide d-group): 512 blocks / 512 warps.
// 16-slot (48KB) smem ring, but wait_group(8): at most 8 committed groups
// (48 x 16B LDGSTS) outstanding per warp — just under the M_max≈55 per-warp
// LSU tracking cap. R8's wait_group(14) allowed 84 outstanding and the LSU
// backpressured the issuing warp (90.8us); R6's wait_group(6) allowed only 36
// (82.4us). This sits at the knee: max in-flight demand without issue stalls.
// Minimal traffic: 3 reads + 1 write = 537MB.

#define BATCH 16
#define TLEN  2048
#define DIM   1024
#define GROUP 32
#define SPB   8                        // steps per ring slot
#define NB    16                       // ring slots (48KB; reuse slack >> lead)
#define WAITG 8                        // max outstanding commit groups (48 tiles)
#define NBT   (TLEN / SPB)             // 256 iterations
#define TILES_PER_THREAD 6             // 3 arr * 8 steps * 8 tiles / 32 thr

__device__ __forceinline__ void cp_async16(uint32_t s, const void* g) {
    asm volatile("cp.async.cg.shared.global [%0], [%1], 16;" :: "r"(s), "l"(g));
}

__global__ __launch_bounds__(GROUP, 4)
void wkv_warp_ring_kernel(const float* __restrict__ K,
                          const float* __restrict__ V,
                          const float* __restrict__ W,
                          float* __restrict__ O) {
    // ring[slot][arr][step][d] : slot<16, arr<3, step<8, d<32  -> 49152 B
    __shared__ float ring[NB * 3 * SPB * GROUP];

    const int tid = threadIdx.x;
    const int b   = blockIdx.x >> 5;          // batch
    const int g   = blockIdx.x & 31;          // d-group of 32

    const size_t rowBase = (size_t)b * TLEN * DIM + (size_t)g * GROUP;
    const uint32_t sBase = (uint32_t)__cvta_generic_to_shared(ring);

    const float* arrs[3] = { K, V, W };

    // Issue all cp.asyncs for one ring slot (8 steps x 3 arrays x 128B rows).
    auto issue_batch = [&](int bt) {
        const int slot = bt & (NB - 1);
        const int step0 = bt * SPB;
#pragma unroll
        for (int j = 0; j < TILES_PER_THREAD; j++) {
            int i   = tid + GROUP * j;        // 0..191
            int arr = i >> 6;                 // /64  (8 tiles * 8 steps per array)
            int rem = i & 63;
            int t   = rem >> 3;               // step within slot
            int col = rem & 7;                // 16B column within 128B row
            size_t goff = rowBase + (size_t)(step0 + t) * DIM + (size_t)col * 4;
            uint32_t soff = (uint32_t)((((slot * 3 + arr) * SPB + t) * GROUP + col * 4) * 4);
            cp_async16(sBase + soff, arrs[arr] + goff);
        }
    };

    // ---- prologue: fill NB-1 ring slots (completion gated by WAITG below) ----
#pragma unroll
    for (int bt = 0; bt < NB - 1; bt++) {
        issue_batch(bt);
        asm volatile("cp.async.commit_group;");
    }

    float a = 0.0f, s = 0.0f;
    float* out = O + rowBase + tid;

    for (int bt = 0; bt < NBT; bt++) {
        // Keep pipeline full; commit every iteration (possibly empty group)
        // so wait_group arithmetic stays uniform through the tail.
        if (bt + NB - 1 < NBT) issue_batch(bt + NB - 1);
        asm volatile("cp.async.commit_group;");
        // <=WAITG newest groups outstanding: slot bt complete (NB-1-WAITG >= 1
        // iterations of slack), 48 LDGSTS in flight < M_max ~55 per warp.
        asm volatile("cp.async.wait_group %0;" :: "n"(WAITG) : "memory");
        __syncwarp();   // this slot's data visible to all lanes

        const int slot = bt & (NB - 1);
        const float* rk = &ring[((slot * 3 + 0) * SPB) * GROUP + tid];
        const float* rv = &ring[((slot * 3 + 1) * SPB) * GROUP + tid];
        const float* rw = &ring[((slot * 3 + 2) * SPB) * GROUP + tid];

#pragma unroll
        for (int u = 0; u < SPB; u++) {
            float lk = rk[u * GROUP];
            float lv = rv[u * GROUP];
            float lw = rw[u * GROUP];
            float ek = __expf(lk);
            float ew = __expf(lw);
            a = fmaf(ew, a, ek);
            s = fmaf(ew, s, ek * lv);
            __stcs(&out[(size_t)(bt * SPB + u) * DIM], __fdividef(s, a));
        }
        __syncwarp();   // all lanes done reading before slot is overwritten
    }
}

extern "C" void kernel_launch(void* const* d_in, const int* in_sizes, int n_in,
                              void* d_out, int out_size) {
    const float* k = (const float*)d_in[0];
    const float* v = (const float*)d_in[1];
    const float* w = (const float*)d_in[2];
    float* out = (float*)d_out;

    wkv_warp_ring_kernel<<<BATCH * (DIM / GROUP), GROUP>>>(k, v, w, out);
}